// round 2
// baseline (speedup 1.0000x reference)
#include <cuda_runtime.h>

#define N_MAX 100000
#define E_MAX 1600000
#define F 128
#define C_OUT 64
#define BN_EPS 1e-5f

// ---------------- scratch (__device__ globals; no allocation allowed) --------
__device__ float d_dinv[N_MAX];
__device__ int   d_cnt[N_MAX];
__device__ int   d_off[N_MAX + 1];
__device__ int   d_cur[N_MAX];
__device__ int   d_esrc[E_MAX];
__device__ float d_ew[E_MAX];
__device__ float d_t[(size_t)N_MAX * F];      // GEMM output
__device__ float d_hr1[(size_t)N_MAX * F];    // layer-1 relu output (pre-BN)
__device__ float d_hr2[(size_t)N_MAX * F];    // layer-2 relu output (pre-BN)
__device__ float d_stats[2 * F];              // col sum, col sumsq
__device__ float d_scale1[F], d_shift1[F];
__device__ float d_scale2[F], d_shift2[F];

static inline int cdiv(int a, int b) { return (a + b - 1) / b; }

// ---------------- CSR build ---------------------------------------------------
__global__ void k_zero_cnt(int n) {
    int i = blockIdx.x * blockDim.x + threadIdx.x;
    if (i < n) d_cnt[i] = 0;
}

__global__ void k_hist(const int* __restrict__ dst, int e) {
    int i = blockIdx.x * blockDim.x + threadIdx.x;
    if (i < e) atomicAdd(&d_cnt[dst[i]], 1);
}

__global__ void k_dinv(int n) {
    int i = blockIdx.x * blockDim.x + threadIdx.x;
    if (i < n) d_dinv[i] = rsqrtf((float)(d_cnt[i] + 1));   // +1 self loop
}

// single-block exclusive scan of d_cnt -> d_off/d_cur (1024 threads, shfl-based)
__global__ void k_scan(int n, int e) {
    __shared__ int warpsum[32];
    __shared__ int carry_s;
    const int tid = threadIdx.x;
    const int lane = tid & 31;
    const int wid = tid >> 5;
    if (tid == 0) carry_s = 0;
    __syncthreads();
    for (int base = 0; base < n; base += 1024) {
        int i = base + tid;
        int v = (i < n) ? d_cnt[i] : 0;
        int x = v;
#pragma unroll
        for (int o = 1; o < 32; o <<= 1) {
            int y = __shfl_up_sync(0xffffffffu, x, o);
            if (lane >= o) x += y;
        }
        if (lane == 31) warpsum[wid] = x;
        __syncthreads();
        if (wid == 0) {
            int ws = warpsum[lane];
            int wx = ws;
#pragma unroll
            for (int o = 1; o < 32; o <<= 1) {
                int y = __shfl_up_sync(0xffffffffu, wx, o);
                if (lane >= o) wx += y;
            }
            warpsum[lane] = wx - ws;   // exclusive warp offsets
        }
        __syncthreads();
        int incl = x + warpsum[wid];
        int exc = carry_s + incl - v;
        if (i < n) { d_off[i] = exc; d_cur[i] = exc; }
        __syncthreads();
        if (tid == 1023) carry_s += incl;   // incl of last thread = chunk total
        __syncthreads();
    }
    if (tid == 0) d_off[n] = e;
}

__global__ void k_scatter(const int* __restrict__ src, const int* __restrict__ dst, int e) {
    int i = blockIdx.x * blockDim.x + threadIdx.x;
    if (i >= e) return;
    int s = src[i], d = dst[i];
    int pos = atomicAdd(&d_cur[d], 1);
    d_esrc[pos] = s;
    d_ew[pos] = d_dinv[s] * d_dinv[d];
}

// ---------------- GEMM: C[n,NOUT] (+)= BN(A)[n,128] @ W[128,NOUT] -------------
// 256 threads, 4x4 register tile. K=128 fully unrolled. Optional per-input-col
// affine (fused BatchNorm apply on A).
template <int NOUT, bool ACC, bool BN>
__global__ __launch_bounds__(256) void k_gemm128(const float* __restrict__ A,
                                                 const float* __restrict__ W,
                                                 float* __restrict__ C, int n,
                                                 const float* __restrict__ scale,
                                                 const float* __restrict__ shift) {
    constexpr int TN = 4, TM = 4;
    constexpr int NTX = NOUT / TN;
    constexpr int NTY = 256 / NTX;
    constexpr int BM = NTY * TM;
    const int tx = threadIdx.x % NTX;
    const int ty = threadIdx.x / NTX;
    const int row0 = blockIdx.x * BM + ty * TM;
    if (row0 >= n) return;                  // n % 4 == 0
    const float* a0 = A + (size_t)row0 * F;
    const float* w0 = W + tx * TN;
    float acc[TM][TN] = {};
#pragma unroll
    for (int k4 = 0; k4 < F / 4; k4++) {
        float4 a[TM];
#pragma unroll
        for (int i = 0; i < TM; i++)
            a[i] = *(const float4*)(a0 + (size_t)i * F + k4 * 4);
        if (BN) {
            float4 sc = ((const float4*)scale)[k4];
            float4 sh = ((const float4*)shift)[k4];
#pragma unroll
            for (int i = 0; i < TM; i++) {
                a[i].x = fmaf(a[i].x, sc.x, sh.x);
                a[i].y = fmaf(a[i].y, sc.y, sh.y);
                a[i].z = fmaf(a[i].z, sc.z, sh.z);
                a[i].w = fmaf(a[i].w, sc.w, sh.w);
            }
        }
#pragma unroll
        for (int kk = 0; kk < 4; kk++) {
            float4 b = *(const float4*)(w0 + (size_t)(k4 * 4 + kk) * NOUT);
            float bv[TN] = {b.x, b.y, b.z, b.w};
#pragma unroll
            for (int i = 0; i < TM; i++) {
                const float* af = (const float*)&a[i];
                float av = af[kk];
#pragma unroll
                for (int j = 0; j < TN; j++)
                    acc[i][j] = fmaf(av, bv[j], acc[i][j]);
            }
        }
    }
#pragma unroll
    for (int i = 0; i < TM; i++) {
        float* cp = C + (size_t)(row0 + i) * NOUT + tx * TN;
        float4 r = make_float4(acc[i][0], acc[i][1], acc[i][2], acc[i][3]);
        if (ACC) {
            float4 o = *(const float4*)cp;
            r.x += o.x; r.y += o.y; r.z += o.z; r.w += o.w;
        }
        *(float4*)cp = r;
    }
}

// ---------------- fused aggregation (F=128) -----------------------------------
// warp per node (grid-stride): acc = dinv(v)^2 * t[v] + sum_j ew[j]*t[esrc[j]]
// then h[v] = relu(acc + bias); per-thread register stats -> one atomic set/thread.
template <bool STATS>
__global__ __launch_bounds__(256) void k_agg128(const float* __restrict__ t,
                                                const float* __restrict__ bias,
                                                float* __restrict__ h, int n) {
    const int lane = threadIdx.x & 31;
    const int warp = (blockIdx.x * blockDim.x + threadIdx.x) >> 5;
    const int nwarp = (gridDim.x * blockDim.x) >> 5;
    float4 b = ((const float4*)bias)[lane];
    float s0 = 0, s1 = 0, s2 = 0, s3 = 0;
    float q0 = 0, q1 = 0, q2 = 0, q3 = 0;
    for (int v = warp; v < n; v += nwarp) {
        float dv = d_dinv[v];
        float4 acc = *(const float4*)(t + (size_t)v * F + lane * 4);
        float w0 = dv * dv;
        acc.x *= w0; acc.y *= w0; acc.z *= w0; acc.w *= w0;
        const int beg = d_off[v], end = d_off[v + 1];
        for (int j = beg; j < end; j++) {
            int sidx = __ldg(d_esrc + j);
            float w = __ldg(d_ew + j);
            float4 r = *(const float4*)(t + (size_t)sidx * F + lane * 4);
            acc.x = fmaf(w, r.x, acc.x);
            acc.y = fmaf(w, r.y, acc.y);
            acc.z = fmaf(w, r.z, acc.z);
            acc.w = fmaf(w, r.w, acc.w);
        }
        acc.x = fmaxf(acc.x + b.x, 0.0f);
        acc.y = fmaxf(acc.y + b.y, 0.0f);
        acc.z = fmaxf(acc.z + b.z, 0.0f);
        acc.w = fmaxf(acc.w + b.w, 0.0f);
        *(float4*)(h + (size_t)v * F + lane * 4) = acc;
        if (STATS) {
            s0 += acc.x; s1 += acc.y; s2 += acc.z; s3 += acc.w;
            q0 += acc.x * acc.x; q1 += acc.y * acc.y;
            q2 += acc.z * acc.z; q3 += acc.w * acc.w;
        }
    }
    if (STATS) {
        int c = lane * 4;
        atomicAdd(&d_stats[c + 0], s0); atomicAdd(&d_stats[c + 1], s1);
        atomicAdd(&d_stats[c + 2], s2); atomicAdd(&d_stats[c + 3], s3);
        atomicAdd(&d_stats[F + c + 0], q0); atomicAdd(&d_stats[F + c + 1], q1);
        atomicAdd(&d_stats[F + c + 2], q2); atomicAdd(&d_stats[F + c + 3], q3);
    }
}

// ---------------- fused aggregation (F=64, final layer) -----------------------
__global__ __launch_bounds__(256) void k_agg64(const float* __restrict__ t,
                                               const float* __restrict__ bias,
                                               float* __restrict__ out, int n) {
    const int lane = threadIdx.x & 31;
    const int warp = (blockIdx.x * blockDim.x + threadIdx.x) >> 5;
    const int nwarp = (gridDim.x * blockDim.x) >> 5;
    float2 b = ((const float2*)bias)[lane];
    for (int v = warp; v < n; v += nwarp) {
        float dv = d_dinv[v];
        float2 acc = *(const float2*)(t + (size_t)v * C_OUT + lane * 2);
        float w0 = dv * dv;
        acc.x *= w0; acc.y *= w0;
        const int beg = d_off[v], end = d_off[v + 1];
        for (int j = beg; j < end; j++) {
            int sidx = __ldg(d_esrc + j);
            float w = __ldg(d_ew + j);
            float2 r = *(const float2*)(t + (size_t)sidx * C_OUT + lane * 2);
            acc.x = fmaf(w, r.x, acc.x);
            acc.y = fmaf(w, r.y, acc.y);
        }
        acc.x = fmaxf(acc.x + b.x, 0.0f);
        acc.y = fmaxf(acc.y + b.y, 0.0f);
        *(float2*)(out + (size_t)v * C_OUT + lane * 2) = acc;
    }
}

// ---------------- BN ----------------------------------------------------------
__global__ void k_zero_stats() { d_stats[threadIdx.x] = 0.0f; }  // 256 threads

__global__ void k_bn_finalize(const float* __restrict__ gamma,
                              const float* __restrict__ beta,
                              float* __restrict__ scale, float* __restrict__ shift,
                              int n) {
    int c = threadIdx.x;                    // 128 threads
    float inv_n = 1.0f / (float)n;
    float m = d_stats[c] * inv_n;
    float var = d_stats[F + c] * inv_n - m * m;
    float rstd = rsqrtf(var + BN_EPS);
    float sc = gamma[c] * rstd;
    scale[c] = sc;
    shift[c] = beta[c] - sc * m;
}

// ---------------- launch ------------------------------------------------------
extern "C" void kernel_launch(void* const* d_in, const int* in_sizes, int n_in,
                              void* d_out, int out_size) {
    const float* x     = (const float*)d_in[0];
    const int*   ei    = (const int*)d_in[1];
    const float* W1    = (const float*)d_in[2];
    const float* b1    = (const float*)d_in[3];
    const float* W2    = (const float*)d_in[4];
    const float* b2    = (const float*)d_in[5];
    const float* Wout  = (const float*)d_in[6];
    const float* bout  = (const float*)d_in[7];
    const float* gamma = (const float*)d_in[8];
    const float* beta  = (const float*)d_in[9];
    float* out = (float*)d_out;

    const int n = in_sizes[0] / F;
    const int e = in_sizes[1] / 2;
    const int* src = ei;
    const int* dst = ei + e;

    float *t, *hr1, *hr2, *sc1, *sh1, *sc2, *sh2;
    cudaGetSymbolAddress((void**)&t, d_t);
    cudaGetSymbolAddress((void**)&hr1, d_hr1);
    cudaGetSymbolAddress((void**)&hr2, d_hr2);
    cudaGetSymbolAddress((void**)&sc1, d_scale1);
    cudaGetSymbolAddress((void**)&sh1, d_shift1);
    cudaGetSymbolAddress((void**)&sc2, d_scale2);
    cudaGetSymbolAddress((void**)&sh2, d_shift2);

    const int TB = 256;
    const int AGG_BLOCKS = 1024;

    // --- CSR build + norm ---
    k_zero_cnt<<<cdiv(n, TB), TB>>>(n);
    k_hist<<<cdiv(e, TB), TB>>>(dst, e);
    k_dinv<<<cdiv(n, TB), TB>>>(n);
    k_scan<<<1, 1024>>>(n, e);
    k_scatter<<<cdiv(e, TB), TB>>>(src, dst, e);

    // --- layer 1: hr1 = relu(agg(x@W1) + b1); BN folded into consumers ---
    k_gemm128<F, false, false><<<cdiv(n, 32), 256>>>(x, W1, t, n, nullptr, nullptr);
    k_zero_stats<<<1, 256>>>();
    k_agg128<true><<<AGG_BLOCKS, TB>>>(t, b1, hr1, n);
    k_bn_finalize<<<1, 128>>>(gamma, beta, sc1, sh1, n);

    // --- layer 2: hr2 = relu(agg(BN(hr1)@W2) + b2) ---
    k_gemm128<F, false, true><<<cdiv(n, 32), 256>>>(hr1, W2, t, n, sc1, sh1);
    k_zero_stats<<<1, 256>>>();
    k_agg128<true><<<AGG_BLOCKS, TB>>>(t, b2, hr2, n);
    k_bn_finalize<<<1, 128>>>(gamma, beta, sc2, sh2, n);

    // --- output: relu(agg([x, BN(hr1), BN(hr2)]@Wout) + bout) ---
    k_gemm128<C_OUT, false, false><<<cdiv(n, 64), 256>>>(x, Wout, t, n, nullptr, nullptr);
    k_gemm128<C_OUT, true, true><<<cdiv(n, 64), 256>>>(hr1, Wout + 128 * C_OUT, t, n, sc1, sh1);
    k_gemm128<C_OUT, true, true><<<cdiv(n, 64), 256>>>(hr2, Wout + 256 * C_OUT, t, n, sc2, sh2);
    k_agg64<<<AGG_BLOCKS, TB>>>(t, bout, out, n);
}